// round 16
// baseline (speedup 1.0000x reference)
#include <cuda_runtime.h>
#include <cuda_fp16.h>
#include <cstdint>

#define DIM 128
#define NLAYERS 4
#define NQ 7
#define TILE_M 64
#define NTHREADS 256
#define KPAD 136      // fp16 elems per smem row (conflict-free ldmatrix)

// ---- device globals ----
__device__ float2 g_U[DIM * DIM];    // U[k][j]
__device__ float2 g_UT[DIM * DIM];   // U^T[j][k]
__device__ __half g_W[DIM * DIM];    // A in fp16, [n][k] (symmetric)
__device__ int g_ctr;                // dynamic tile counter

__device__ __forceinline__ float2 cmul(float2 a, float2 b) {
    return make_float2(a.x * b.x - a.y * b.y, a.x * b.y + a.y * b.x);
}
__device__ __forceinline__ float2 cadd(float2 a, float2 b) {
    return make_float2(a.x + b.x, a.y + b.y);
}

// ---------------------------------------------------------------------------
// Kernel 1: build U, one WARP per column. COMPACT code: runtime bit masks,
// no unrolling -> small SASS, no cold-I$ streaming penalty.
// amp index t = h*32 + lane; qubit q <-> bit (6-q).
// ---------------------------------------------------------------------------
__global__ void build_u_kernel(const float* __restrict__ w) {
    __shared__ float2 gm[NLAYERS * NQ][4];
    const int tid = threadIdx.x;
    const int lane = tid & 31;
    const int wid = tid >> 5;
    const int j = blockIdx.x * 4 + wid;

    if (tid < NLAYERS * NQ) {
        const float phi = w[tid * 3 + 0];
        const float th  = w[tid * 3 + 1];
        const float om  = w[tid * 3 + 2];
        float sh, ch; sincosf(0.5f * th, &sh, &ch);
        float sap, cap, sam, cam;
        sincosf(0.5f * (phi + om), &sap, &cap);
        sincosf(0.5f * (phi - om), &sam, &cam);
        gm[tid][0] = make_float2( cap * ch, -sap * ch);
        gm[tid][1] = make_float2(-cam * sh, -sam * sh);
        gm[tid][2] = make_float2( cam * sh, -sam * sh);
        gm[tid][3] = make_float2( cap * ch,  sap * ch);
    }
    __syncthreads();

    float2 a[4];
    #pragma unroll
    for (int h = 0; h < 4; h++)
        a[h] = make_float2((h * 32 + lane) == j ? 1.f : 0.f, 0.f);

    #pragma unroll 1
    for (int l = 0; l < NLAYERS; l++) {
        #pragma unroll 1
        for (int q = 0; q < NQ; q++) {
            const int g = l * NQ + q;
            const float2 u00 = gm[g][0], u01 = gm[g][1];
            const float2 u10 = gm[g][2], u11 = gm[g][3];
            const int b = 1 << (6 - q);
            if (b >= 32) {
                const int hp = b >> 5;
                #pragma unroll 1
                for (int h0 = 0; h0 < 4; h0++) {
                    if (!(h0 & hp)) {
                        const int h1 = h0 | hp;
                        const float2 a0 = a[h0], a1 = a[h1];
                        a[h0] = cadd(cmul(u00, a0), cmul(u01, a1));
                        a[h1] = cadd(cmul(u10, a0), cmul(u11, a1));
                    }
                }
            } else {
                #pragma unroll 1
                for (int h = 0; h < 4; h++) {
                    float2 p;
                    p.x = __shfl_xor_sync(0xffffffffu, a[h].x, b);
                    p.y = __shfl_xor_sync(0xffffffffu, a[h].y, b);
                    const float2 s = a[h];
                    if (lane & b) a[h] = cadd(cmul(u10, p), cmul(u11, s));
                    else          a[h] = cadd(cmul(u00, s), cmul(u01, p));
                }
            }
        }
        const int r = (l % (NQ - 1)) + 1;
        #pragma unroll 1
        for (int c = 0; c < NQ; c++) {
            const int t = (c + r) % NQ;
            const int cb = 1 << (6 - c);
            const int tb = 1 << (6 - t);
            if (tb >= 32) {
                const int hb = tb >> 5;
                #pragma unroll 1
                for (int h0 = 0; h0 < 4; h0++) {
                    if (h0 & hb) continue;
                    const bool ctrl = (cb >= 32) ? ((h0 & (cb >> 5)) != 0)
                                                 : ((lane & cb) != 0);
                    if (ctrl) {
                        const float2 tmp = a[h0];
                        a[h0] = a[h0 | hb];
                        a[h0 | hb] = tmp;
                    }
                }
            } else {
                #pragma unroll 1
                for (int h = 0; h < 4; h++) {
                    float2 p;
                    p.x = __shfl_xor_sync(0xffffffffu, a[h].x, tb);
                    p.y = __shfl_xor_sync(0xffffffffu, a[h].y, tb);
                    const bool ctrl = (cb >= 32) ? ((h & (cb >> 5)) != 0)
                                                 : ((lane & cb) != 0);
                    if (ctrl) a[h] = p;
                }
            }
        }
    }
    #pragma unroll 1
    for (int h = 0; h < 4; h++) {
        const int idx = h * 32 + lane;
        g_U[idx * DIM + j] = a[h];
        g_UT[j * DIM + idx] = a[h];
    }
}

// ---------------------------------------------------------------------------
// Kernel 2: A[i][j] = sum_k d_k * Re(conj(U[k][i]) U[k][j]); fp16.
// Also resets the dynamic tile counter for the main kernel.
// ---------------------------------------------------------------------------
__global__ void build_w_kernel() {
    __shared__ float2 ui[DIM];
    const int i = blockIdx.x;
    const int j = threadIdx.x;
    if (i == 0 && j == 0) g_ctr = 0;
    ui[j] = g_UT[i * DIM + j];
    __syncthreads();
    float acc = 0.f;
    #pragma unroll 4
    for (int k = 0; k < DIM; k++) {
        const float dk = (((k >> 6) ^ k) & 1) ? -1.f : 1.f;
        const float2 uj = g_U[k * DIM + j];
        acc += dk * (ui[k].x * uj.x + ui[k].y * uj.y);
    }
    g_W[i * DIM + j] = __float2half_rn(acc);
}

// ---------------------------------------------------------------------------
// Main kernel: ONE MMA segment y1 = A*xhi; symmetry: x^T A x =
// (xhi + 2*xlo)^T y1 + O(2^-22). B-fragments ntp=0 resident in registers.
// ---------------------------------------------------------------------------
#define SM_ZHI 0
#define SM_ZLO 17408
#define SM_W   34816
#define SM_PD  69632
#define SM_PS  70656
#define SM_NEXT 71680
#define SM_TOTAL 71696

__device__ __forceinline__ void ldsm4(uint32_t& r0, uint32_t& r1, uint32_t& r2,
                                      uint32_t& r3, uint32_t addr) {
    asm volatile("ldmatrix.sync.aligned.m8n8.x4.shared.b16 {%0,%1,%2,%3}, [%4];"
                 : "=r"(r0), "=r"(r1), "=r"(r2), "=r"(r3) : "r"(addr));
}
__device__ __forceinline__ void mma16816(float* d, const uint32_t* a, const uint32_t* b) {
    asm volatile(
        "mma.sync.aligned.m16n8k16.row.col.f32.f16.f16.f32 "
        "{%0,%1,%2,%3}, {%4,%5,%6,%7}, {%8,%9}, {%0,%1,%2,%3};"
        : "+f"(d[0]), "+f"(d[1]), "+f"(d[2]), "+f"(d[3])
        : "r"(a[0]), "r"(a[1]), "r"(a[2]), "r"(a[3]), "r"(b[0]), "r"(b[1]));
}
__device__ __forceinline__ uint32_t pack2h(float a, float b) {
    const __half2 h = __floats2half2_rn(a, b);
    return *(const uint32_t*)&h;
}

__global__ void __launch_bounds__(NTHREADS, 2)
vqa_main_kernel(const float* __restrict__ x, float* __restrict__ out, int ntiles) {
    extern __shared__ char smem[];
    const uint32_t sbase = (uint32_t)__cvta_generic_to_shared(smem);
    float* pd = (float*)(smem + SM_PD);
    float* ps = (float*)(smem + SM_PS);
    int* nxt = (int*)(smem + SM_NEXT);

    const int tid = threadIdx.x;
    const int lane = tid & 31;
    const int wid = tid >> 5;
    const int mi = wid & 1;   // m-stripe (32 rows)
    const int nh = wid >> 1;  // n-quarter (32 cols)

    // ---- load W (fp16 A) into padded smem, once per CTA ----
    {
        const uint2* w_g = (const uint2*)g_W;
        for (int idx = tid; idx < DIM * 32; idx += NTHREADS) {
            const int i = idx >> 5, c = idx & 31;
            *(uint2*)(smem + SM_W + i * (KPAD * 2) + c * 8) = w_g[idx];
        }
    }

    // ldmatrix lane base addresses (bytes)
    const uint32_t abase = sbase + SM_ZHI +
        (uint32_t)(((32 * mi + (lane & 15)) * KPAD + 8 * (lane >> 4)) * 2);
    const int rowL = (lane & 7) + ((lane >> 4) & 1) * 8;
    const int kL = ((lane >> 3) & 1) * 8;
    const uint32_t bbase = sbase + SM_W +
        (uint32_t)(((32 * nh + rowL) * KPAD + kL) * 2);

    __syncthreads();

    // ---- preload B fragments for ntp=0 (resident across all tiles) ----
    uint32_t b0[8][4];
    #pragma unroll
    for (int kk = 0; kk < 8; kk++)
        ldsm4(b0[kk][0], b0[kk][1], b0[kk][2], b0[kk][3],
              bbase + (uint32_t)(kk * 32));

    // ---- first tile via dynamic counter ----
    if (tid == 0) *nxt = atomicAdd(&g_ctr, 1);
    __syncthreads();
    int tile = *nxt;

    while (tile < ntiles) {
        if (tid == 0) *nxt = atomicAdd(&g_ctr, 1);

        // ---- phase 1: load + convert (pure streaming) ----
        const float4* xt = (const float4*)x + (size_t)tile * (TILE_M * 32);
        #pragma unroll
        for (int rr = 0; rr < 8; rr++) {
            const int row = wid * 8 + rr;
            const float4 vv = xt[row * 32 + lane];
            const float hx = __half2float(__float2half_rn(vv.x));
            const float hy = __half2float(__float2half_rn(vv.y));
            const float hz = __half2float(__float2half_rn(vv.z));
            const float hw = __half2float(__float2half_rn(vv.w));
            *(uint2*)(smem + SM_ZHI + row * (KPAD * 2) + lane * 8) =
                make_uint2(pack2h(hx, hy), pack2h(hz, hw));
            *(uint2*)(smem + SM_ZLO + row * (KPAD * 2) + lane * 8) =
                make_uint2(pack2h(vv.x - hx, vv.y - hy), pack2h(vv.z - hz, vv.w - hw));
        }
        __syncthreads();

        // ---- phase 2: GEMM, single segment y1 = A * xhi ----
        float d[2][4][4];
        #pragma unroll
        for (int mt = 0; mt < 2; mt++)
            #pragma unroll
            for (int nt = 0; nt < 4; nt++)
                #pragma unroll
                for (int q = 0; q < 4; q++) d[mt][nt][q] = 0.f;

        #pragma unroll
        for (int kk = 0; kk < 8; kk++) {
            const uint32_t ko = (uint32_t)(kk * 32);  // 16 elems * 2B
            uint32_t ah0[4], ah1[4];
            ldsm4(ah0[0], ah0[1], ah0[2], ah0[3], abase + ko);
            ldsm4(ah1[0], ah1[1], ah1[2], ah1[3], abase + ko + 16 * KPAD * 2);
            uint32_t b1[4];
            ldsm4(b1[0], b1[1], b1[2], b1[3],
                  bbase + ko + (uint32_t)(16 * KPAD * 2));
            // ntp = 0 (resident fragments)
            mma16816(d[0][0], ah0, &b0[kk][0]);
            mma16816(d[0][1], ah0, &b0[kk][2]);
            mma16816(d[1][0], ah1, &b0[kk][0]);
            mma16816(d[1][1], ah1, &b0[kk][2]);
            // ntp = 1
            mma16816(d[0][2], ah0, &b1[0]);
            mma16816(d[0][3], ah0, &b1[2]);
            mma16816(d[1][2], ah1, &b1[0]);
            mma16816(d[1][3], ah1, &b1[2]);
        }

        // ---- phase 3: epilogue — num = (xhi+2*xlo).y1 ; den = (xhi+xlo)^2 ----
        const int tq = lane & 3;
        const int tr = lane >> 2;
        float racc[4] = {0.f, 0.f, 0.f, 0.f};
        float sacc[4] = {0.f, 0.f, 0.f, 0.f};
        #pragma unroll
        for (int mt = 0; mt < 2; mt++) {
            const int row0 = 32 * mi + 16 * mt + tr;
            #pragma unroll
            for (int nt = 0; nt < 4; nt++) {
                const int c = 32 * nh + 8 * nt + 2 * tq;
                const int o0 = (row0 * KPAD + c) * 2;
                const int o1 = ((row0 + 8) * KPAD + c) * 2;
                const float2 h0 = __half22float2(*(__half2*)(smem + SM_ZHI + o0));
                const float2 l0 = __half22float2(*(__half2*)(smem + SM_ZLO + o0));
                const float2 h1 = __half22float2(*(__half2*)(smem + SM_ZHI + o1));
                const float2 l1 = __half22float2(*(__half2*)(smem + SM_ZLO + o1));
                const float x0a = h0.x + l0.x, x0b = h0.y + l0.y;
                const float x1a = h1.x + l1.x, x1b = h1.y + l1.y;
                const float w0a = x0a + l0.x, w0b = x0b + l0.y;
                const float w1a = x1a + l1.x, w1b = x1b + l1.y;
                racc[2 * mt]     += d[mt][nt][0] * w0a + d[mt][nt][1] * w0b;
                racc[2 * mt + 1] += d[mt][nt][2] * w1a + d[mt][nt][3] * w1b;
                sacc[2 * mt]     += x0a * x0a + x0b * x0b;
                sacc[2 * mt + 1] += x1a * x1a + x1b * x1b;
            }
        }
        #pragma unroll
        for (int q = 0; q < 4; q++) {
            racc[q] += __shfl_xor_sync(0xffffffffu, racc[q], 1);
            racc[q] += __shfl_xor_sync(0xffffffffu, racc[q], 2);
            sacc[q] += __shfl_xor_sync(0xffffffffu, sacc[q], 1);
            sacc[q] += __shfl_xor_sync(0xffffffffu, sacc[q], 2);
        }
        if (tq == 0) {
            #pragma unroll
            for (int q = 0; q < 4; q++) {
                const int row = 32 * mi + 8 * q + tr;
                pd[row * 4 + nh] = racc[q];
                ps[row * 4 + nh] = sacc[q];
            }
        }
        __syncthreads();
        int newtile = *nxt;   // read between barriers
        if (tid < TILE_M) {
            const float num = pd[tid * 4] + pd[tid * 4 + 1] +
                              pd[tid * 4 + 2] + pd[tid * 4 + 3];
            const float den = ps[tid * 4] + ps[tid * 4 + 1] +
                              ps[tid * 4 + 2] + ps[tid * 4 + 3];
            out[(size_t)tile * TILE_M + tid] = num / den;
        }
        __syncthreads();
        tile = newtile;
    }
}

// ---------------------------------------------------------------------------
extern "C" void kernel_launch(void* const* d_in, const int* in_sizes, int n_in,
                              void* d_out, int out_size) {
    const float* x = (const float*)d_in[0];
    const float* w = (const float*)d_in[1];
    float* out = (float*)d_out;

    cudaFuncSetAttribute(vqa_main_kernel,
                         cudaFuncAttributeMaxDynamicSharedMemorySize, SM_TOTAL);
    cudaFuncSetAttribute(vqa_main_kernel,
                         cudaFuncAttributePreferredSharedMemoryCarveout, 100);

    build_u_kernel<<<DIM / 4, 128>>>(w);
    build_w_kernel<<<DIM, DIM>>>();

    const int rows = in_sizes[0] / DIM;
    const int ntiles = rows / TILE_M;
    vqa_main_kernel<<<304, NTHREADS, SM_TOTAL>>>(x, out, ntiles);
}